// round 13
// baseline (speedup 1.0000x reference)
#include <cuda_runtime.h>
#include <cuda_bf16.h>
#include <math.h>

// DecodeSBP: per-keypoint argmax over sigmoid heatmaps.
// x: [1, 133, 512, 512] fp32.  out: [133,3] = (x*4, y*4, conf) or (-4,-4,-1).
// sigmoid monotonic -> argmax(sigmoid) == argmax; sigmoid only on the max.
//
// Round 12: two-kernel split. K1 = single wave of 266 CTAs x 512 threads
// (2 CTAs per keypoint, keypoint-aligned halves, all 148 SMs streaming,
// proven batched-load codegen) ending in ONE plain STG of a 64-bit key per
// CTA -- no atomics, no fences, no counter, no serialized decode tail (which
// cost R10 ~2us). K2 = one tiny CTA that merges 2 keys per keypoint and
// decodes. Graph edge orders K1 -> K2.
// Key = (monotonic float bits << 32) | ~local_idx: max key == max value with
// smallest index on ties (jnp.argmax first-occurrence semantics).

#define KPTS   133
#define HW     (512 * 512)
#define HW4    65536                 // float4 per keypoint
#define W      512
#define SCALE  4.0f
#define CONF_THRESHOLD 0.8f

#define NT      512
#define HALVES  2
#define NBLOCKS (KPTS * HALVES)      // 266
#define HALF_V  (HW4 / HALVES)       // 32768 float4 per half
#define UB      8
#define GROUPS  (HALF_V / (NT * UB)) // 8 groups x 8 = 64 iters/thread

__device__ unsigned long long g_partials[NBLOCKS];

__device__ __forceinline__ unsigned int float_to_key(float f) {
    unsigned int u = __float_as_uint(f);
    return u ^ ((unsigned int)((int)u >> 31) | 0x80000000u);
}
__device__ __forceinline__ float key_to_float(unsigned int k) {
    unsigned int u = (k & 0x80000000u) ? (k ^ 0x80000000u) : ~k;
    return __uint_as_float(u);
}

__global__ __launch_bounds__(NT, 2)
void sbp_scan_kernel(const float* __restrict__ x) {
    const int h = blockIdx.x;        // 0..265
    const int k = h >> 1;
    const int half = h & 1;
    const float4* __restrict__ p =
        reinterpret_cast<const float4*>(x + (size_t)k * HW) + half * HALF_V;

    const int tid = threadIdx.x;

    float best = -INFINITY;
    int bidx = 0;

    // 8 groups x (8 back-to-back streaming LDG.128 -> compares).
    // Per-thread indices strictly increase -> '>' keeps first occurrence.
    #pragma unroll
    for (int g = 0; g < GROUPS; g++) {
        const int base = g * (NT * UB) + tid;
        float4 v[UB];
        #pragma unroll
        for (int u = 0; u < UB; u++)
            v[u] = __ldcs(p + base + u * NT);
        #pragma unroll
        for (int u = 0; u < UB; u++) {
            const int b = (base + u * NT) << 2;
            if (v[u].x > best) { best = v[u].x; bidx = b;     }
            if (v[u].y > best) { best = v[u].y; bidx = b + 1; }
            if (v[u].z > best) { best = v[u].z; bidx = b + 2; }
            if (v[u].w > best) { best = v[u].w; bidx = b + 3; }
        }
    }
    bidx += half * (HALF_V << 2);    // local index within keypoint

    unsigned long long key =
        ((unsigned long long)float_to_key(best) << 32) | (unsigned int)(~bidx);

    #pragma unroll
    for (int off = 16; off > 0; off >>= 1) {
        unsigned long long o = __shfl_down_sync(0xFFFFFFFFu, key, off);
        if (o > key) key = o;
    }

    __shared__ unsigned long long s_key[NT / 32];
    const int lane = tid & 31;
    const int wid  = tid >> 5;
    if (lane == 0) s_key[wid] = key;
    __syncthreads();

    if (tid == 0) {
        #pragma unroll
        for (int w = 1; w < NT / 32; w++)
            if (s_key[w] > key) key = s_key[w];
        g_partials[h] = key;         // plain store; graph edge orders K2
    }
}

__global__ void sbp_decode_kernel(float* __restrict__ out) {
    const int k = threadIdx.x;
    if (k < KPTS) {
        unsigned long long m = g_partials[2 * k];
        const unsigned long long m2 = g_partials[2 * k + 1];
        if (m2 > m) m = m2;
        const float mv  = key_to_float((unsigned int)(m >> 32));
        const int   idx = (int)~(unsigned int)(m & 0xFFFFFFFFu);
        const float conf = 1.0f / (1.0f + __expf(-mv));
        const bool valid = conf > CONF_THRESHOLD;
        const float yy = (float)(idx / W);
        const float xx = (float)(idx % W);
        // Invalid rows: (-1,-1,-1) then x,y scaled -> (-4,-4,-1).
        out[k * 3 + 0] = valid ? xx * SCALE : -SCALE;
        out[k * 3 + 1] = valid ? yy * SCALE : -SCALE;
        out[k * 3 + 2] = valid ? conf : -1.0f;
    }
}

extern "C" void kernel_launch(void* const* d_in, const int* in_sizes, int n_in,
                              void* d_out, int out_size) {
    const float* x = (const float*)d_in[0];
    float* out = (float*)d_out;
    sbp_scan_kernel<<<NBLOCKS, NT>>>(x);
    sbp_decode_kernel<<<1, 256>>>(out);
}

// round 16
// speedup vs baseline: 1.0431x; 1.0431x over previous
#include <cuda_runtime.h>
#include <cuda_bf16.h>
#include <math.h>

// DecodeSBP: per-keypoint argmax over sigmoid heatmaps.  FINAL (converged).
// x: [1, 133, 512, 512] fp32.  out: [133,3] = (x*4, y*4, conf) or (-4,-4,-1).
// sigmoid monotonic -> argmax(sigmoid) == argmax; sigmoid only on the max.
//
// 13 rounds of structural search established:
//  - one CTA per keypoint (133 x 1024), literal-bound branch-free grid-stride
//    loop, direct output write is the fastest shape (74% DRAM, 25.3us);
//  - every cross-CTA merge (atomicMax+tail: +2us; second kernel: +3.7us
//    launch) costs more than the 15 idle SMs it recovers;
//  - runtime loop bounds or body branches collapse DRAM% to 43-57;
//  - explicit load batching, occupancy changes, __ldcs are neutral here;
//  - per-SM streaming (43.8 GB/s) is the best observed in any configuration:
//    the residual vs 8 TB/s spec is HBM device efficiency, not schedulable.

#define KPTS 133
#define HW   (512 * 512)        // 262144 elements per keypoint
#define HW4  (HW / 4)           // 65536 float4 per keypoint
#define NTHREADS 1024
#define W 512
#define SCALE 4.0f              // INPUT_SIZE(2048) / W(512)
#define CONF_THRESHOLD 0.8f

__global__ __launch_bounds__(NTHREADS, 1)
void decode_sbp_kernel(const float* __restrict__ x, float* __restrict__ out) {
    const int k = blockIdx.x;
    const float4* __restrict__ p =
        reinterpret_cast<const float4*>(x + (size_t)k * HW);

    const int tid = threadIdx.x;

    float best = -INFINITY;
    int bidx = 0;

    // 64 iterations per thread; strictly increasing indices, so strict '>'
    // preserves the first-occurrence tie-break of jnp.argmax.
    #pragma unroll 8
    for (int i = tid; i < HW4; i += NTHREADS) {
        float4 v = __ldcs(p + i);
        const int base = i << 2;
        if (v.x > best) { best = v.x; bidx = base;     }
        if (v.y > best) { best = v.y; bidx = base + 1; }
        if (v.z > best) { best = v.z; bidx = base + 2; }
        if (v.w > best) { best = v.w; bidx = base + 3; }
    }

    // Warp reduction: max value, ties broken by smaller index (first occurrence).
    #pragma unroll
    for (int off = 16; off > 0; off >>= 1) {
        float v2 = __shfl_down_sync(0xFFFFFFFFu, best, off);
        int   i2 = __shfl_down_sync(0xFFFFFFFFu, bidx, off);
        if (v2 > best || (v2 == best && i2 < bidx)) { best = v2; bidx = i2; }
    }

    __shared__ float s_val[32];
    __shared__ int   s_idx[32];

    const int lane = tid & 31;
    const int wid  = tid >> 5;
    if (lane == 0) { s_val[wid] = best; s_idx[wid] = bidx; }
    __syncthreads();

    // Final reduce over 32 warp results in warp 0.
    if (wid == 0) {
        best = s_val[lane];
        bidx = s_idx[lane];
        #pragma unroll
        for (int off = 16; off > 0; off >>= 1) {
            float v2 = __shfl_down_sync(0xFFFFFFFFu, best, off);
            int   i2 = __shfl_down_sync(0xFFFFFFFFu, bidx, off);
            if (v2 > best || (v2 == best && i2 < bidx)) { best = v2; bidx = i2; }
        }
        if (lane == 0) {
            const float conf = 1.0f / (1.0f + __expf(-best));
            const bool valid = conf > CONF_THRESHOLD;
            const float yy = (float)(bidx / W);
            const float xx = (float)(bidx % W);
            // Reference: invalid rows are (-1,-1,-1), then x,y columns scaled
            // for ALL rows -> invalid rows become (-4,-4,-1).
            out[k * 3 + 0] = valid ? xx * SCALE : -SCALE;
            out[k * 3 + 1] = valid ? yy * SCALE : -SCALE;
            out[k * 3 + 2] = valid ? conf : -1.0f;
        }
    }
}

extern "C" void kernel_launch(void* const* d_in, const int* in_sizes, int n_in,
                              void* d_out, int out_size) {
    const float* x = (const float*)d_in[0];
    float* out = (float*)d_out;
    decode_sbp_kernel<<<KPTS, NTHREADS>>>(x, out);
}

// round 17
// speedup vs baseline: 1.0560x; 1.0125x over previous
#include <cuda_runtime.h>
#include <cuda_bf16.h>
#include <math.h>
#include <cstdint>

// DecodeSBP: per-keypoint argmax over sigmoid heatmaps.
// x: [1, 133, 512, 512] fp32.  out: [133,3] = (x*4, y*4, conf) or (-4,-4,-1).
// sigmoid monotonic -> argmax(sigmoid) == argmax; sigmoid only on the max.
//
// Round 17: 2-CTA CLUSTER per keypoint. Previous multi-CTA merges paid +2us
// (global atomics + counter tail, R10) or +3.7us (second kernel, R13). DSMEM
// merge costs ~0.5us total: rank 1 stores its 64-bit key into rank 0's smem
// (st.shared::cluster), cluster barrier, rank 0 merges 2 keys and writes the
// output directly. 266 CTAs x 512 threads = single wave at 2 CTAs/SM, all
// 148 SMs streaming, keypoint-aligned halves, proven batched-load codegen.
// Key = (monotonic float bits << 32) | ~local_idx: max key == max value with
// smallest index on ties (jnp.argmax first-occurrence semantics).

#define KPTS   133
#define HW     (512 * 512)
#define HW4    65536                 // float4 per keypoint
#define W      512
#define SCALE  4.0f
#define CONF_THRESHOLD 0.8f

#define NT      512
#define NBLOCKS (KPTS * 2)           // 266
#define HALF_V  (HW4 / 2)            // 32768 float4 per half
#define UB      8
#define GROUPS  (HALF_V / (NT * UB)) // 8 groups x 8 = 64 iters/thread

__device__ __forceinline__ unsigned int float_to_key(float f) {
    unsigned int u = __float_as_uint(f);
    return u ^ ((unsigned int)((int)u >> 31) | 0x80000000u);
}
__device__ __forceinline__ float key_to_float(unsigned int k) {
    unsigned int u = (k & 0x80000000u) ? (k ^ 0x80000000u) : ~k;
    return __uint_as_float(u);
}

__global__ __launch_bounds__(NT, 2) __cluster_dims__(2, 1, 1)
void decode_sbp_kernel(const float* __restrict__ x, float* __restrict__ out) {
    __shared__ unsigned long long s_key[NT / 32];
    __shared__ unsigned long long s_remote;   // written by rank 1 via DSMEM

    const int k    = blockIdx.x >> 1;         // keypoint
    uint32_t rank;
    asm("mov.u32 %0, %%cluster_ctarank;" : "=r"(rank));
    const float4* __restrict__ p =
        reinterpret_cast<const float4*>(x + (size_t)k * HW) + rank * HALF_V;

    const int tid = threadIdx.x;

    float best = -INFINITY;
    int bidx = 0;

    // 8 groups x (8 back-to-back streaming LDG.128 -> compares).
    // Per-thread indices strictly increase -> '>' keeps first occurrence.
    #pragma unroll
    for (int g = 0; g < GROUPS; g++) {
        const int base = g * (NT * UB) + tid;
        float4 v[UB];
        #pragma unroll
        for (int u = 0; u < UB; u++)
            v[u] = __ldcs(p + base + u * NT);
        #pragma unroll
        for (int u = 0; u < UB; u++) {
            const int b = (base + u * NT) << 2;
            if (v[u].x > best) { best = v[u].x; bidx = b;     }
            if (v[u].y > best) { best = v[u].y; bidx = b + 1; }
            if (v[u].z > best) { best = v[u].z; bidx = b + 2; }
            if (v[u].w > best) { best = v[u].w; bidx = b + 3; }
        }
    }
    bidx += (int)rank * (HALF_V << 2);        // local index within keypoint

    unsigned long long key =
        ((unsigned long long)float_to_key(best) << 32) | (unsigned int)(~bidx);

    #pragma unroll
    for (int off = 16; off > 0; off >>= 1) {
        unsigned long long o = __shfl_down_sync(0xFFFFFFFFu, key, off);
        if (o > key) key = o;
    }

    const int lane = tid & 31;
    const int wid  = tid >> 5;
    if (lane == 0) s_key[wid] = key;
    __syncthreads();

    if (tid == 0) {
        #pragma unroll
        for (int w = 1; w < NT / 32; w++)
            if (s_key[w] > key) key = s_key[w];
        if (rank == 1) {
            // Push our key into rank 0's s_remote via DSMEM.
            uint32_t laddr;
            asm("{ .reg .u64 t; cvta.to.shared.u64 t, %1; cvt.u32.u64 %0, t; }"
                : "=r"(laddr) : "l"(&s_remote));
            asm volatile(
                "{ .reg .b32 r;\n\t"
                "mapa.shared::cluster.u32 r, %0, 0;\n\t"
                "st.shared::cluster.u64 [r], %1; }"
                :: "r"(laddr), "l"(key) : "memory");
        } else {
            s_key[0] = key;                   // park rank 0's own result
        }
    }

    // Cluster barrier: release on arrive / acquire on wait orders the DSMEM
    // store before rank 0's read. All threads of both CTAs participate.
    asm volatile("barrier.cluster.arrive.aligned;" ::: "memory");
    asm volatile("barrier.cluster.wait.aligned;"   ::: "memory");

    if (rank == 0 && tid == 0) {
        unsigned long long m = s_key[0];
        if (s_remote > m) m = s_remote;
        const float mv  = key_to_float((unsigned int)(m >> 32));
        const int   idx = (int)~(unsigned int)(m & 0xFFFFFFFFu);
        const float conf = 1.0f / (1.0f + __expf(-mv));
        const bool valid = conf > CONF_THRESHOLD;
        const float yy = (float)(idx / W);
        const float xx = (float)(idx % W);
        // Invalid rows: (-1,-1,-1) then x,y scaled -> (-4,-4,-1).
        out[k * 3 + 0] = valid ? xx * SCALE : -SCALE;
        out[k * 3 + 1] = valid ? yy * SCALE : -SCALE;
        out[k * 3 + 2] = valid ? conf : -1.0f;
    }
}

extern "C" void kernel_launch(void* const* d_in, const int* in_sizes, int n_in,
                              void* d_out, int out_size) {
    const float* x = (const float*)d_in[0];
    float* out = (float*)d_out;
    decode_sbp_kernel<<<NBLOCKS, NT>>>(x, out);
}